// round 1
// baseline (speedup 1.0000x reference)
#include <cuda_runtime.h>
#include <math.h>
#include <math_constants.h>

// Problem constants
#define BB  2
#define TT  2048
#define DDIM 1024
#define HH  16
#define DHH 64
#define MM  (BB*TT)   // 4096 rows for all projections

// ---------------------------------------------------------------------------
// Scratch (device globals; no runtime allocation allowed)
// ---------------------------------------------------------------------------
__device__ float g_q[(size_t)MM * DDIM];
__device__ float g_k[(size_t)MM * DDIM];
__device__ float g_v[(size_t)MM * DDIM];
__device__ float g_att[(size_t)MM * DDIM];
__device__ float g_sin[TT * 32];
__device__ float g_cos[TT * 32];

// ---------------------------------------------------------------------------
// RoPE sin/cos table: angle(t, jj) = t * 10000^(-2*jj/64), jj in [0,32)
// Computed in fp64 so our trig error is far below the 1e-3 budget.
// ---------------------------------------------------------------------------
__global__ void sincos_kernel() {
    int idx = blockIdx.x * blockDim.x + threadIdx.x;
    if (idx >= TT * 32) return;
    int t  = idx >> 5;
    int jj = idx & 31;
    double ang = (double)t * pow(10000.0, -2.0 * (double)jj / 64.0);
    g_sin[idx] = (float)sin(ang);
    g_cos[idx] = (float)cos(ang);
}

// ---------------------------------------------------------------------------
// SGEMM with bias: C[M,N] = A[M,K] @ B[K,N] + bias[N]
// Classic 128x128x8 tiling, 256 threads, 8x8 per thread.
// M,N,K all multiples of 128/128/8 here -> no bounds checks.
// ---------------------------------------------------------------------------
__global__ void __launch_bounds__(256) sgemm_bias(
    const float* __restrict__ A, const float* __restrict__ Bm,
    const float* __restrict__ bias, float* __restrict__ C,
    int M, int N, int K)
{
    __shared__ float As[8][128];   // transposed: As[k][m]
    __shared__ float Bs[8][128];   // Bs[k][n]

    const int tid = threadIdx.x;
    const int bm = blockIdx.y * 128;
    const int bn = blockIdx.x * 128;

    const int arow = tid >> 1;          // 0..127
    const int acol = (tid & 1) * 4;     // 0 or 4
    const int brow = tid >> 5;          // 0..7
    const int bcol = (tid & 31) * 4;    // 0..124

    const int tx = tid & 15;
    const int ty = tid >> 4;

    float acc[8][8];
#pragma unroll
    for (int i = 0; i < 8; i++)
#pragma unroll
        for (int j = 0; j < 8; j++) acc[i][j] = 0.f;

    const float* Aptr = A + (size_t)(bm + arow) * K + acol;
    const float* Bptr = Bm + (size_t)brow * N + bn + bcol;

    for (int k0 = 0; k0 < K; k0 += 8) {
        float4 a4 = *(const float4*)(Aptr + k0);
        As[acol + 0][arow] = a4.x;
        As[acol + 1][arow] = a4.y;
        As[acol + 2][arow] = a4.z;
        As[acol + 3][arow] = a4.w;
        float4 b4 = *(const float4*)(Bptr + (size_t)k0 * N);
        *(float4*)&Bs[brow][bcol] = b4;
        __syncthreads();

#pragma unroll
        for (int kk = 0; kk < 8; kk++) {
            float4 a0 = *(const float4*)&As[kk][ty * 4];
            float4 a1 = *(const float4*)&As[kk][64 + ty * 4];
            float4 b0 = *(const float4*)&Bs[kk][tx * 4];
            float4 b1 = *(const float4*)&Bs[kk][64 + tx * 4];
            float ar[8] = {a0.x, a0.y, a0.z, a0.w, a1.x, a1.y, a1.z, a1.w};
            float br[8] = {b0.x, b0.y, b0.z, b0.w, b1.x, b1.y, b1.z, b1.w};
#pragma unroll
            for (int i = 0; i < 8; i++)
#pragma unroll
                for (int j = 0; j < 8; j++)
                    acc[i][j] += ar[i] * br[j];
        }
        __syncthreads();
    }

    // Epilogue: bias + store (float4)
#pragma unroll
    for (int ii = 0; ii < 2; ii++) {
#pragma unroll
        for (int i = 0; i < 4; i++) {
            int m = bm + ii * 64 + ty * 4 + i;
#pragma unroll
            for (int jj = 0; jj < 2; jj++) {
                int c0 = bn + jj * 64 + tx * 4;
                float4 bia = *(const float4*)&bias[c0];
                float4 o;
                o.x = acc[ii * 4 + i][jj * 4 + 0] + bia.x;
                o.y = acc[ii * 4 + i][jj * 4 + 1] + bia.y;
                o.z = acc[ii * 4 + i][jj * 4 + 2] + bia.z;
                o.w = acc[ii * 4 + i][jj * 4 + 3] + bia.w;
                *(float4*)&C[(size_t)m * N + c0] = o;
            }
        }
    }
}

// ---------------------------------------------------------------------------
// RoPE in-place on Q and K. Layout [B,T,H*DH]. repeat-2 sin/cos,
// rotate_half = half-split:
//   out[j]    = u[j]   *cos[j]    - u[j+32]*sin[j]      (j in [0,32))
//   out[j+32] = u[j+32]*cos[j+32] + u[j]   *sin[j+32]
// cos[j] indexes table at jj=j>>1; cos[j+32] at jj=(j>>1)+16.
// ---------------------------------------------------------------------------
__global__ void rope_kernel() {
    int idx = blockIdx.x * blockDim.x + threadIdx.x;
    const int total = BB * TT * HH * 32;
    if (idx >= total) return;
    int j = idx & 31;
    int h = (idx >> 5) & (HH - 1);
    int t = (idx >> 9) & (TT - 1);
    int b = idx >> 20;

    size_t off = ((size_t)(b * TT + t)) * DDIM + h * DHH;
    int ti = t * 32;
    float c1 = g_cos[ti + (j >> 1)];
    float s1 = g_sin[ti + (j >> 1)];
    float c2 = g_cos[ti + (j >> 1) + 16];
    float s2 = g_sin[ti + (j >> 1) + 16];

    float q1 = g_q[off + j], q2 = g_q[off + j + 32];
    g_q[off + j]      = q1 * c1 - q2 * s1;
    g_q[off + j + 32] = q2 * c2 + q1 * s2;

    float k1 = g_k[off + j], k2 = g_k[off + j + 32];
    g_k[off + j]      = k1 * c1 - k2 * s1;
    g_k[off + j + 32] = k2 * c2 + k1 * s2;
}

// ---------------------------------------------------------------------------
// Flash attention, causal. Block = (qtile, h, b), 256 threads.
// 64x64 tiles, 4x4 fragment per thread (16x16 thread grid).
// Online softmax; masked score exactly -10000 to match reference.
// ---------------------------------------------------------------------------
#define ALD 68  // padded row stride (floats) for smem tiles

__global__ void __launch_bounds__(256) attn_kernel() {
    extern __shared__ float smem[];
    float* Qs = smem;                 // [64][ALD]
    float* Ks = Qs + 64 * ALD;
    float* Vs = Ks + 64 * ALD;
    float* Ps = Vs + 64 * ALD;

    const int q0  = blockIdx.x * 64;
    const int h   = blockIdx.y;
    const int b   = blockIdx.z;
    const int tid = threadIdx.x;
    const int tx  = tid & 15;
    const int ty  = tid >> 4;

    const size_t base = (size_t)b * TT * DDIM + (size_t)h * DHH;

    // Load Q tile
    for (int i = tid; i < 64 * 16; i += 256) {
        int r = i >> 4, c4 = (i & 15) * 4;
        *(float4*)&Qs[r * ALD + c4] =
            *(const float4*)&g_q[base + (size_t)(q0 + r) * DDIM + c4];
    }

    float m_[4], l_[4], o[4][4];
#pragma unroll
    for (int i = 0; i < 4; i++) {
        m_[i] = -CUDART_INF_F;
        l_[i] = 0.f;
#pragma unroll
        for (int j = 0; j < 4; j++) o[i][j] = 0.f;
    }
    __syncthreads();

    for (int k0 = 0; k0 <= q0; k0 += 64) {
        // Load K, V tiles
        for (int i = tid; i < 64 * 16; i += 256) {
            int r = i >> 4, c4 = (i & 15) * 4;
            size_t g = base + (size_t)(k0 + r) * DDIM + c4;
            *(float4*)&Ks[r * ALD + c4] = *(const float4*)&g_k[g];
            *(float4*)&Vs[r * ALD + c4] = *(const float4*)&g_v[g];
        }
        __syncthreads();

        // S = Q @ K^T  (4x4 fragment)
        float s[4][4];
#pragma unroll
        for (int i = 0; i < 4; i++)
#pragma unroll
            for (int j = 0; j < 4; j++) s[i][j] = 0.f;

#pragma unroll
        for (int d0 = 0; d0 < 64; d0 += 4) {
            float4 qv[4], kv[4];
#pragma unroll
            for (int i = 0; i < 4; i++)
                qv[i] = *(const float4*)&Qs[(ty * 4 + i) * ALD + d0];
#pragma unroll
            for (int j = 0; j < 4; j++)
                kv[j] = *(const float4*)&Ks[(tx * 4 + j) * ALD + d0];
#pragma unroll
            for (int i = 0; i < 4; i++)
#pragma unroll
                for (int j = 0; j < 4; j++)
                    s[i][j] += qv[i].x * kv[j].x + qv[i].y * kv[j].y +
                               qv[i].z * kv[j].z + qv[i].w * kv[j].w;
        }

        // scale + causal mask (reference replaces masked scores with -10000)
        const float scale = 0.125f;  // 1/sqrt(64)
#pragma unroll
        for (int i = 0; i < 4; i++) {
            int qg = q0 + ty * 4 + i;
#pragma unroll
            for (int j = 0; j < 4; j++) {
                int kg = k0 + tx * 4 + j;
                float v = s[i][j] * scale;
                s[i][j] = (kg > qg) ? -10000.0f : v;
            }
        }

        // online softmax (row reduce across 16 tx lanes via shfl.xor)
#pragma unroll
        for (int i = 0; i < 4; i++) {
            float rm = fmaxf(fmaxf(s[i][0], s[i][1]), fmaxf(s[i][2], s[i][3]));
#pragma unroll
            for (int off = 1; off < 16; off <<= 1)
                rm = fmaxf(rm, __shfl_xor_sync(0xffffffffu, rm, off));
            float newm = fmaxf(m_[i], rm);
            float alpha = __expf(m_[i] - newm);
            m_[i] = newm;
            float rs = 0.f;
#pragma unroll
            for (int j = 0; j < 4; j++) {
                float p = __expf(s[i][j] - newm);
                s[i][j] = p;
                rs += p;
            }
#pragma unroll
            for (int off = 1; off < 16; off <<= 1)
                rs += __shfl_xor_sync(0xffffffffu, rs, off);
            l_[i] = l_[i] * alpha + rs;
#pragma unroll
            for (int j = 0; j < 4; j++) o[i][j] *= alpha;
        }

        // write P fragment to smem
#pragma unroll
        for (int i = 0; i < 4; i++)
#pragma unroll
            for (int j = 0; j < 4; j++)
                Ps[(ty * 4 + i) * ALD + tx * 4 + j] = s[i][j];
        __syncthreads();

        // O += P @ V
#pragma unroll
        for (int kk = 0; kk < 64; kk += 4) {
            float4 pv[4], vv[4];
#pragma unroll
            for (int i = 0; i < 4; i++)
                pv[i] = *(const float4*)&Ps[(ty * 4 + i) * ALD + kk];
#pragma unroll
            for (int j = 0; j < 4; j++)
                vv[j] = *(const float4*)&Vs[(kk + j) * ALD + tx * 4];
#pragma unroll
            for (int i = 0; i < 4; i++) {
                o[i][0] += pv[i].x * vv[0].x + pv[i].y * vv[1].x +
                           pv[i].z * vv[2].x + pv[i].w * vv[3].x;
                o[i][1] += pv[i].x * vv[0].y + pv[i].y * vv[1].y +
                           pv[i].z * vv[2].y + pv[i].w * vv[3].y;
                o[i][2] += pv[i].x * vv[0].z + pv[i].y * vv[1].z +
                           pv[i].z * vv[2].z + pv[i].w * vv[3].z;
                o[i][3] += pv[i].x * vv[0].w + pv[i].y * vv[1].w +
                           pv[i].z * vv[2].w + pv[i].w * vv[3].w;
            }
        }
        __syncthreads();
    }

    // normalize + write out in [B,T,H*DH] layout (ready for final GEMM)
#pragma unroll
    for (int i = 0; i < 4; i++) {
        float inv = 1.0f / l_[i];
        float4 ov;
        ov.x = o[i][0] * inv;
        ov.y = o[i][1] * inv;
        ov.z = o[i][2] * inv;
        ov.w = o[i][3] * inv;
        size_t row = (size_t)b * TT + q0 + ty * 4 + i;
        *(float4*)&g_att[row * DDIM + h * DHH + tx * 4] = ov;
    }
}

// ---------------------------------------------------------------------------
// Launch
// ---------------------------------------------------------------------------
extern "C" void kernel_launch(void* const* d_in, const int* in_sizes, int n_in,
                              void* d_out, int out_size)
{
    const float* x  = (const float*)d_in[0];
    // d_in[1] = mask (causal, known shape -> ignored)
    const float* wq = (const float*)d_in[2];
    const float* bq = (const float*)d_in[3];
    const float* wk = (const float*)d_in[4];
    const float* bk = (const float*)d_in[5];
    const float* wv = (const float*)d_in[6];
    const float* bv = (const float*)d_in[7];
    const float* wo = (const float*)d_in[8];
    const float* bo = (const float*)d_in[9];
    float* out = (float*)d_out;

    float *qp, *kp, *vp, *ap;
    cudaGetSymbolAddress((void**)&qp, g_q);
    cudaGetSymbolAddress((void**)&kp, g_k);
    cudaGetSymbolAddress((void**)&vp, g_v);
    cudaGetSymbolAddress((void**)&ap, g_att);

    // sin/cos table
    sincos_kernel<<<(TT * 32 + 255) / 256, 256>>>();

    // QKV projections
    dim3 ggrid(DDIM / 128, MM / 128);
    sgemm_bias<<<ggrid, 256>>>(x, wq, bq, qp, MM, DDIM, DDIM);
    sgemm_bias<<<ggrid, 256>>>(x, wk, bk, kp, MM, DDIM, DDIM);
    sgemm_bias<<<ggrid, 256>>>(x, wv, bv, vp, MM, DDIM, DDIM);

    // RoPE on Q,K
    const int rope_n = BB * TT * HH * 32;
    rope_kernel<<<(rope_n + 255) / 256, 256>>>();

    // attention
    const int smem_bytes = 4 * 64 * ALD * sizeof(float);  // 69632
    cudaFuncSetAttribute(attn_kernel,
                         cudaFuncAttributeMaxDynamicSharedMemorySize, smem_bytes);
    attn_kernel<<<dim3(TT / 64, HH, BB), 256, smem_bytes>>>();

    // output projection -> d_out
    sgemm_bias<<<ggrid, 256>>>(ap, wo, bo, out, MM, DDIM, DDIM);
}

// round 3
// speedup vs baseline: 1.2357x; 1.2357x over previous
#include <cuda_runtime.h>
#include <cuda_bf16.h>
#include <math.h>
#include <math_constants.h>
#include <cstdint>

// Problem constants
#define BB  2
#define TT  2048
#define DDIM 1024
#define HH  16
#define DHH 64
#define MM  (BB*TT)   // 4096 rows for all projections

// ---------------------------------------------------------------------------
// Scratch (device globals; no runtime allocation allowed)
// ---------------------------------------------------------------------------
__device__ float g_q[(size_t)MM * DDIM];
__device__ float g_k[(size_t)MM * DDIM];
__device__ float g_v[(size_t)MM * DDIM];
__device__ float g_att[(size_t)MM * DDIM];
__device__ float g_sin[TT * 32];
__device__ float g_cos[TT * 32];

// bf16 split buffers
__device__ __nv_bfloat16 g_ahi[(size_t)MM * DDIM];
__device__ __nv_bfloat16 g_alo[(size_t)MM * DDIM];
__device__ __nv_bfloat16 g_whi[(size_t)4 * DDIM * DDIM]; // weights transposed [N,K]
__device__ __nv_bfloat16 g_wlo[(size_t)4 * DDIM * DDIM];

// ---------------------------------------------------------------------------
// Warp-level tensor helpers (baseline PTX: ldmatrix + mma.sync, sm_80 class)
// ---------------------------------------------------------------------------
__device__ __forceinline__ uint32_t smem_u32(const void* p) {
    uint32_t a;
    asm("{ .reg .u64 t; cvta.to.shared.u64 t, %1; cvt.u32.u64 %0, t; }"
        : "=r"(a) : "l"(p));
    return a;
}

__device__ __forceinline__ void ldm_x4(uint32_t* r, uint32_t addr) {
    asm volatile("ldmatrix.sync.aligned.m8n8.x4.shared.b16 {%0,%1,%2,%3}, [%4];"
                 : "=r"(r[0]), "=r"(r[1]), "=r"(r[2]), "=r"(r[3]) : "r"(addr));
}

__device__ __forceinline__ void mma16816(float* c, const uint32_t* a,
                                         const uint32_t* b) {
    asm volatile(
        "mma.sync.aligned.m16n8k16.row.col.f32.bf16.bf16.f32 "
        "{%0,%1,%2,%3}, {%4,%5,%6,%7}, {%8,%9}, {%0,%1,%2,%3};"
        : "+f"(c[0]), "+f"(c[1]), "+f"(c[2]), "+f"(c[3])
        : "r"(a[0]), "r"(a[1]), "r"(a[2]), "r"(a[3]), "r"(b[0]), "r"(b[1]));
}

// ---------------------------------------------------------------------------
// RoPE sin/cos table (fp64 trig, far below 1e-3 budget)
// ---------------------------------------------------------------------------
__global__ void sincos_kernel() {
    int idx = blockIdx.x * blockDim.x + threadIdx.x;
    if (idx >= TT * 32) return;
    int t  = idx >> 5;
    int jj = idx & 31;
    double ang = (double)t * pow(10000.0, -2.0 * (double)jj / 64.0);
    g_sin[idx] = (float)sin(ang);
    g_cos[idx] = (float)cos(ang);
}

// ---------------------------------------------------------------------------
// fp32 -> bf16 hi/lo split (elementwise)
// ---------------------------------------------------------------------------
__global__ void split_kernel(const float* __restrict__ src,
                             __nv_bfloat16* __restrict__ hi,
                             __nv_bfloat16* __restrict__ lo, int n) {
    int i = blockIdx.x * blockDim.x + threadIdx.x;
    if (i >= n) return;
    float v = src[i];
    __nv_bfloat16 h = __float2bfloat16(v);
    hi[i] = h;
    lo[i] = __float2bfloat16(v - __bfloat162float(h));
}

// fp32 W[K,N] -> bf16 hi/lo transposed [N,K]
__global__ void splitT_kernel(const float* __restrict__ w,
                              __nv_bfloat16* __restrict__ hi,
                              __nv_bfloat16* __restrict__ lo) {
    __shared__ float tile[32][33];
    int bx = blockIdx.x * 32;  // n-dim
    int by = blockIdx.y * 32;  // k-dim
    int tx = threadIdx.x, ty = threadIdx.y;  // 32 x 8
#pragma unroll
    for (int i = 0; i < 32; i += 8)
        tile[ty + i][tx] = w[(size_t)(by + ty + i) * DDIM + bx + tx];
    __syncthreads();
#pragma unroll
    for (int i = 0; i < 32; i += 8) {
        float v = tile[tx][ty + i];  // = w[by+tx][bx+ty+i]
        size_t o = (size_t)(bx + ty + i) * DDIM + by + tx;
        __nv_bfloat16 h = __float2bfloat16(v);
        hi[o] = h;
        lo[o] = __float2bfloat16(v - __bfloat162float(h));
    }
}

// ---------------------------------------------------------------------------
// Tensor-core GEMM via mma.sync (bf16 3-pass split, fp32 accum):
// C[M,N] = (Ahi+Alo)[M,K] @ (Bhi+Blo)[N,K]^T + bias
// Block 128x128, 8 warps (warp tile 64x32), kTile=32.
// ---------------------------------------------------------------------------
#define KP 40  // padded smem row stride (bf16): conflict-free ldmatrix

__global__ void __launch_bounds__(256) mma_gemm(
    const __nv_bfloat16* __restrict__ Ah, const __nv_bfloat16* __restrict__ Al,
    const __nv_bfloat16* __restrict__ Bh, const __nv_bfloat16* __restrict__ Bl,
    const float* __restrict__ bias, float* __restrict__ C)
{
    __shared__ __nv_bfloat16 sAh[128][KP], sAl[128][KP];
    __shared__ __nv_bfloat16 sBh[128][KP], sBl[128][KP];

    const int tid = threadIdx.x;
    const int lane = tid & 31;
    const int wid = tid >> 5;
    const int wm = (wid & 1) * 64;   // warp m-offset within block
    const int wn = (wid >> 1) * 32;  // warp n-offset within block
    const int bn = blockIdx.x * 128;
    const int bm = blockIdx.y * 128;

    float acc[4][4][4];
#pragma unroll
    for (int i = 0; i < 4; i++)
#pragma unroll
        for (int j = 0; j < 4; j++)
#pragma unroll
            for (int r = 0; r < 4; r++) acc[i][j][r] = 0.f;

    // ldmatrix source addresses (lane-dependent, loop-invariant parts)
    const int a_row = lane & 15;            // + wm + mf*16
    const int a_kof = (lane >> 4) << 3;     // 0 or 8, + ko
    const int b_n   = (lane & 7) + ((lane >> 4) << 3);  // + wn + pair*16
    const int b_kof = ((lane >> 3) & 1) << 3;           // 0 or 8, + ko

    const int ld_row = tid >> 2;       // 0..63
    const int ld_cg  = (tid & 3) * 8;  // 0,8,16,24

    for (int kt = 0; kt < 32; kt++) {
        const int k0 = kt * 32;
        // Stage 128x32 bf16 tiles for all 4 operand matrices
#pragma unroll
        for (int half = 0; half < 2; half++) {
            int row = half * 64 + ld_row;
            size_t ga = (size_t)(bm + row) * DDIM + k0 + ld_cg;
            size_t gb = (size_t)(bn + row) * DDIM + k0 + ld_cg;
            *(uint4*)&sAh[row][ld_cg] = *(const uint4*)(Ah + ga);
            *(uint4*)&sAl[row][ld_cg] = *(const uint4*)(Al + ga);
            *(uint4*)&sBh[row][ld_cg] = *(const uint4*)(Bh + gb);
            *(uint4*)&sBl[row][ld_cg] = *(const uint4*)(Bl + gb);
        }
        __syncthreads();

#pragma unroll
        for (int ko = 0; ko < 32; ko += 16) {
            // B fragments (hi & lo): 2 x ldmatrix.x4 each -> 4 frags of 2 regs
            uint32_t bh[4][2], bl[4][2];
#pragma unroll
            for (int p = 0; p < 2; p++) {
                uint32_t t4[4];
                uint32_t addr = smem_u32(&sBh[wn + p * 16 + b_n][ko + b_kof]);
                ldm_x4(t4, addr);
                bh[p * 2][0] = t4[0]; bh[p * 2][1] = t4[1];
                bh[p * 2 + 1][0] = t4[2]; bh[p * 2 + 1][1] = t4[3];
                addr = smem_u32(&sBl[wn + p * 16 + b_n][ko + b_kof]);
                ldm_x4(t4, addr);
                bl[p * 2][0] = t4[0]; bl[p * 2][1] = t4[1];
                bl[p * 2 + 1][0] = t4[2]; bl[p * 2 + 1][1] = t4[3];
            }
#pragma unroll
            for (int mf = 0; mf < 4; mf++) {
                uint32_t ahr[4], alr[4];
                ldm_x4(ahr, smem_u32(&sAh[wm + mf * 16 + a_row][ko + a_kof]));
                ldm_x4(alr, smem_u32(&sAl[wm + mf * 16 + a_row][ko + a_kof]));
#pragma unroll
                for (int nf = 0; nf < 4; nf++) {
                    mma16816(acc[mf][nf], ahr, bh[nf]);
                    mma16816(acc[mf][nf], ahr, bl[nf]);
                    mma16816(acc[mf][nf], alr, bh[nf]);
                }
            }
        }
        __syncthreads();
    }

    // Epilogue: frag layout c0,c1 at (row=lane/4, col=2*(lane%4)), c2,c3 at row+8
    const int qr = lane >> 2;
    const int qc = (lane & 3) * 2;
#pragma unroll
    for (int mf = 0; mf < 4; mf++) {
#pragma unroll
        for (int nf = 0; nf < 4; nf++) {
            int col = bn + wn + nf * 8 + qc;
            float b0 = bias[col], b1 = bias[col + 1];
            int r0 = bm + wm + mf * 16 + qr;
            float2 v0 = {acc[mf][nf][0] + b0, acc[mf][nf][1] + b1};
            float2 v1 = {acc[mf][nf][2] + b0, acc[mf][nf][3] + b1};
            *(float2*)&C[(size_t)r0 * DDIM + col] = v0;
            *(float2*)&C[(size_t)(r0 + 8) * DDIM + col] = v1;
        }
    }
}

// ---------------------------------------------------------------------------
// RoPE in-place on Q and K
// ---------------------------------------------------------------------------
__global__ void rope_kernel() {
    int idx = blockIdx.x * blockDim.x + threadIdx.x;
    const int total = BB * TT * HH * 32;
    if (idx >= total) return;
    int j = idx & 31;
    int h = (idx >> 5) & (HH - 1);
    int t = (idx >> 9) & (TT - 1);
    int b = idx >> 20;

    size_t off = ((size_t)(b * TT + t)) * DDIM + h * DHH;
    int ti = t * 32;
    float c1 = g_cos[ti + (j >> 1)];
    float s1 = g_sin[ti + (j >> 1)];
    float c2 = g_cos[ti + (j >> 1) + 16];
    float s2 = g_sin[ti + (j >> 1) + 16];

    float q1 = g_q[off + j], q2 = g_q[off + j + 32];
    g_q[off + j]      = q1 * c1 - q2 * s1;
    g_q[off + j + 32] = q2 * c2 + q1 * s2;

    float k1 = g_k[off + j], k2 = g_k[off + j + 32];
    g_k[off + j]      = k1 * c1 - k2 * s1;
    g_k[off + j + 32] = k2 * c2 + k1 * s2;
}

// ---------------------------------------------------------------------------
// Flash attention, causal (fp32 FFMA; next round's target)
// ---------------------------------------------------------------------------
#define ALD 68

__global__ void __launch_bounds__(256) attn_kernel() {
    extern __shared__ float smemf[];
    float* Qs = smemf;
    float* Ks = Qs + 64 * ALD;
    float* Vs = Ks + 64 * ALD;
    float* Ps = Vs + 64 * ALD;

    const int q0  = blockIdx.x * 64;
    const int h   = blockIdx.y;
    const int b   = blockIdx.z;
    const int tid = threadIdx.x;
    const int tx  = tid & 15;
    const int ty  = tid >> 4;

    const size_t base = (size_t)b * TT * DDIM + (size_t)h * DHH;

    for (int i = tid; i < 64 * 16; i += 256) {
        int r = i >> 4, c4 = (i & 15) * 4;
        *(float4*)&Qs[r * ALD + c4] =
            *(const float4*)&g_q[base + (size_t)(q0 + r) * DDIM + c4];
    }

    float m_[4], l_[4], o[4][4];
#pragma unroll
    for (int i = 0; i < 4; i++) {
        m_[i] = -CUDART_INF_F;
        l_[i] = 0.f;
#pragma unroll
        for (int j = 0; j < 4; j++) o[i][j] = 0.f;
    }
    __syncthreads();

    for (int k0 = 0; k0 <= q0; k0 += 64) {
        for (int i = tid; i < 64 * 16; i += 256) {
            int r = i >> 4, c4 = (i & 15) * 4;
            size_t g = base + (size_t)(k0 + r) * DDIM + c4;
            *(float4*)&Ks[r * ALD + c4] = *(const float4*)&g_k[g];
            *(float4*)&Vs[r * ALD + c4] = *(const float4*)&g_v[g];
        }
        __syncthreads();

        float s[4][4];
#pragma unroll
        for (int i = 0; i < 4; i++)
#pragma unroll
            for (int j = 0; j < 4; j++) s[i][j] = 0.f;

#pragma unroll
        for (int d0 = 0; d0 < 64; d0 += 4) {
            float4 qv[4], kv[4];
#pragma unroll
            for (int i = 0; i < 4; i++)
                qv[i] = *(const float4*)&Qs[(ty * 4 + i) * ALD + d0];
#pragma unroll
            for (int j = 0; j < 4; j++)
                kv[j] = *(const float4*)&Ks[(tx * 4 + j) * ALD + d0];
#pragma unroll
            for (int i = 0; i < 4; i++)
#pragma unroll
                for (int j = 0; j < 4; j++)
                    s[i][j] += qv[i].x * kv[j].x + qv[i].y * kv[j].y +
                               qv[i].z * kv[j].z + qv[i].w * kv[j].w;
        }

        const float scale = 0.125f;
#pragma unroll
        for (int i = 0; i < 4; i++) {
            int qg = q0 + ty * 4 + i;
#pragma unroll
            for (int j = 0; j < 4; j++) {
                int kg = k0 + tx * 4 + j;
                float v = s[i][j] * scale;
                s[i][j] = (kg > qg) ? -10000.0f : v;
            }
        }

#pragma unroll
        for (int i = 0; i < 4; i++) {
            float rm = fmaxf(fmaxf(s[i][0], s[i][1]), fmaxf(s[i][2], s[i][3]));
#pragma unroll
            for (int off = 1; off < 16; off <<= 1)
                rm = fmaxf(rm, __shfl_xor_sync(0xffffffffu, rm, off));
            float newm = fmaxf(m_[i], rm);
            float alpha = __expf(m_[i] - newm);
            m_[i] = newm;
            float rs = 0.f;
#pragma unroll
            for (int j = 0; j < 4; j++) {
                float p = __expf(s[i][j] - newm);
                s[i][j] = p;
                rs += p;
            }
#pragma unroll
            for (int off = 1; off < 16; off <<= 1)
                rs += __shfl_xor_sync(0xffffffffu, rs, off);
            l_[i] = l_[i] * alpha + rs;
#pragma unroll
            for (int j = 0; j < 4; j++) o[i][j] *= alpha;
        }

#pragma unroll
        for (int i = 0; i < 4; i++)
#pragma unroll
            for (int j = 0; j < 4; j++)
                Ps[(ty * 4 + i) * ALD + tx * 4 + j] = s[i][j];
        __syncthreads();

#pragma unroll
        for (int kk = 0; kk < 64; kk += 4) {
            float4 pv[4], vv[4];
#pragma unroll
            for (int i = 0; i < 4; i++)
                pv[i] = *(const float4*)&Ps[(ty * 4 + i) * ALD + kk];
#pragma unroll
            for (int j = 0; j < 4; j++)
                vv[j] = *(const float4*)&Vs[(kk + j) * ALD + tx * 4];
#pragma unroll
            for (int i = 0; i < 4; i++) {
                o[i][0] += pv[i].x * vv[0].x + pv[i].y * vv[1].x +
                           pv[i].z * vv[2].x + pv[i].w * vv[3].x;
                o[i][1] += pv[i].x * vv[0].y + pv[i].y * vv[1].y +
                           pv[i].z * vv[2].y + pv[i].w * vv[3].y;
                o[i][2] += pv[i].x * vv[0].z + pv[i].y * vv[1].z +
                           pv[i].z * vv[2].z + pv[i].w * vv[3].z;
                o[i][3] += pv[i].x * vv[0].w + pv[i].y * vv[1].w +
                           pv[i].z * vv[2].w + pv[i].w * vv[3].w;
            }
        }
        __syncthreads();
    }

#pragma unroll
    for (int i = 0; i < 4; i++) {
        float inv = 1.0f / l_[i];
        float4 ov;
        ov.x = o[i][0] * inv;
        ov.y = o[i][1] * inv;
        ov.z = o[i][2] * inv;
        ov.w = o[i][3] * inv;
        size_t row = (size_t)b * TT + q0 + ty * 4 + i;
        *(float4*)&g_att[row * DDIM + h * DHH + tx * 4] = ov;
    }
}

// ---------------------------------------------------------------------------
// Launch
// ---------------------------------------------------------------------------
extern "C" void kernel_launch(void* const* d_in, const int* in_sizes, int n_in,
                              void* d_out, int out_size)
{
    const float* x  = (const float*)d_in[0];
    const float* wq = (const float*)d_in[2];
    const float* bq = (const float*)d_in[3];
    const float* wk = (const float*)d_in[4];
    const float* bk = (const float*)d_in[5];
    const float* wv = (const float*)d_in[6];
    const float* bv = (const float*)d_in[7];
    const float* wo = (const float*)d_in[8];
    const float* bo = (const float*)d_in[9];
    float* out = (float*)d_out;

    float *qp, *kp, *vp, *ap;
    __nv_bfloat16 *ahi, *alo, *whi, *wlo;
    cudaGetSymbolAddress((void**)&qp, g_q);
    cudaGetSymbolAddress((void**)&kp, g_k);
    cudaGetSymbolAddress((void**)&vp, g_v);
    cudaGetSymbolAddress((void**)&ap, g_att);
    cudaGetSymbolAddress((void**)&ahi, g_ahi);
    cudaGetSymbolAddress((void**)&alo, g_alo);
    cudaGetSymbolAddress((void**)&whi, g_whi);
    cudaGetSymbolAddress((void**)&wlo, g_wlo);

    const size_t WSZ = (size_t)DDIM * DDIM;

    sincos_kernel<<<(TT * 32 + 255) / 256, 256>>>();

    // splits
    const int n_act = MM * DDIM;
    split_kernel<<<(n_act + 255) / 256, 256>>>(x, ahi, alo, n_act);
    dim3 tgrid(32, 32), tblk(32, 8);
    splitT_kernel<<<tgrid, tblk>>>(wq, whi + 0 * WSZ, wlo + 0 * WSZ);
    splitT_kernel<<<tgrid, tblk>>>(wk, whi + 1 * WSZ, wlo + 1 * WSZ);
    splitT_kernel<<<tgrid, tblk>>>(wv, whi + 2 * WSZ, wlo + 2 * WSZ);
    splitT_kernel<<<tgrid, tblk>>>(wo, whi + 3 * WSZ, wlo + 3 * WSZ);

    // tensor-core projections
    dim3 ggrid(DDIM / 128, MM / 128);
    mma_gemm<<<ggrid, 256>>>(ahi, alo, whi + 0 * WSZ, wlo + 0 * WSZ, bq, qp);
    mma_gemm<<<ggrid, 256>>>(ahi, alo, whi + 1 * WSZ, wlo + 1 * WSZ, bk, kp);
    mma_gemm<<<ggrid, 256>>>(ahi, alo, whi + 2 * WSZ, wlo + 2 * WSZ, bv, vp);

    // RoPE
    const int rope_n = BB * TT * HH * 32;
    rope_kernel<<<(rope_n + 255) / 256, 256>>>();

    // attention (fp32 flash)
    const int attn_smem = 4 * 64 * ALD * sizeof(float);
    cudaFuncSetAttribute(attn_kernel,
                         cudaFuncAttributeMaxDynamicSharedMemorySize, attn_smem);
    attn_kernel<<<dim3(TT / 64, HH, BB), 256, attn_smem>>>();

    // out-projection
    split_kernel<<<(n_act + 255) / 256, 256>>>(ap, ahi, alo, n_act);
    mma_gemm<<<ggrid, 256>>>(ahi, alo, whi + 3 * WSZ, wlo + 3 * WSZ, bo, out);
}

// round 6
// speedup vs baseline: 2.2015x; 1.7815x over previous
#include <cuda_runtime.h>
#include <cuda_bf16.h>
#include <math.h>
#include <math_constants.h>
#include <cstdint>

// Problem constants
#define BB  2
#define TT  2048
#define DDIM 1024
#define HH  16
#define DHH 64
#define MM  (BB*TT)

// ---------------------------------------------------------------------------
// Scratch (device globals)
// ---------------------------------------------------------------------------
__device__ float g_q[(size_t)MM * DDIM];
__device__ float g_k[(size_t)MM * DDIM];
__device__ float g_v[(size_t)MM * DDIM];
__device__ float g_att[(size_t)MM * DDIM];
__device__ float g_sin[TT * 32];
__device__ float g_cos[TT * 32];

__device__ __nv_bfloat16 g_ahi[(size_t)MM * DDIM];
__device__ __nv_bfloat16 g_alo[(size_t)MM * DDIM];
__device__ __nv_bfloat16 g_whi[(size_t)4 * DDIM * DDIM];
__device__ __nv_bfloat16 g_wlo[(size_t)4 * DDIM * DDIM];

// attention bf16 operands
__device__ __nv_bfloat16 g_qhi[(size_t)MM * DDIM];
__device__ __nv_bfloat16 g_qlo[(size_t)MM * DDIM];
__device__ __nv_bfloat16 g_khi[(size_t)MM * DDIM];
__device__ __nv_bfloat16 g_klo[(size_t)MM * DDIM];
__device__ __nv_bfloat16 g_vthi[(size_t)MM * DDIM];  // [b,h,dh,T]
__device__ __nv_bfloat16 g_vtlo[(size_t)MM * DDIM];

// ---------------------------------------------------------------------------
// Warp tensor helpers (baseline PTX: ldmatrix + mma.sync)
// ---------------------------------------------------------------------------
__device__ __forceinline__ uint32_t smem_u32(const void* p) {
    uint32_t a;
    asm("{ .reg .u64 t; cvta.to.shared.u64 t, %1; cvt.u32.u64 %0, t; }"
        : "=r"(a) : "l"(p));
    return a;
}

__device__ __forceinline__ void ldm_x4(uint32_t* r, uint32_t addr) {
    asm volatile("ldmatrix.sync.aligned.m8n8.x4.shared.b16 {%0,%1,%2,%3}, [%4];"
                 : "=r"(r[0]), "=r"(r[1]), "=r"(r[2]), "=r"(r[3]) : "r"(addr));
}

__device__ __forceinline__ void mma16816(float* c, const uint32_t* a,
                                         const uint32_t* b) {
    asm volatile(
        "mma.sync.aligned.m16n8k16.row.col.f32.bf16.bf16.f32 "
        "{%0,%1,%2,%3}, {%4,%5,%6,%7}, {%8,%9}, {%0,%1,%2,%3};"
        : "+f"(c[0]), "+f"(c[1]), "+f"(c[2]), "+f"(c[3])
        : "r"(a[0]), "r"(a[1]), "r"(a[2]), "r"(a[3]), "r"(b[0]), "r"(b[1]));
}

__device__ __forceinline__ uint32_t cvt_bf2(float lo, float hi) {
    uint32_t r;
    asm("cvt.rn.bf16x2.f32 %0, %1, %2;" : "=r"(r) : "f"(hi), "f"(lo));
    return r;
}
__device__ __forceinline__ float2 unpack_bf2(uint32_t v) {
    __nv_bfloat162 b = *reinterpret_cast<__nv_bfloat162*>(&v);
    return __bfloat1622float2(b);  // .x = low
}

// ---------------------------------------------------------------------------
// RoPE sin/cos table
// ---------------------------------------------------------------------------
__global__ void sincos_kernel() {
    int idx = blockIdx.x * blockDim.x + threadIdx.x;
    if (idx >= TT * 32) return;
    int t  = idx >> 5;
    int jj = idx & 31;
    double ang = (double)t * pow(10000.0, -2.0 * (double)jj / 64.0);
    g_sin[idx] = (float)sin(ang);
    g_cos[idx] = (float)cos(ang);
}

// ---------------------------------------------------------------------------
// fp32 -> bf16 hi/lo split (elementwise)
// ---------------------------------------------------------------------------
__global__ void split_kernel(const float* __restrict__ src,
                             __nv_bfloat16* __restrict__ hi,
                             __nv_bfloat16* __restrict__ lo, int n) {
    int i = blockIdx.x * blockDim.x + threadIdx.x;
    if (i >= n) return;
    float v = src[i];
    __nv_bfloat16 h = __float2bfloat16(v);
    hi[i] = h;
    lo[i] = __float2bfloat16(v - __bfloat162float(h));
}

// fp32 W[K,N] -> bf16 hi/lo transposed [N,K]
__global__ void splitT_kernel(const float* __restrict__ w,
                              __nv_bfloat16* __restrict__ hi,
                              __nv_bfloat16* __restrict__ lo) {
    __shared__ float tile[32][33];
    int bx = blockIdx.x * 32;
    int by = blockIdx.y * 32;
    int tx = threadIdx.x, ty = threadIdx.y;
#pragma unroll
    for (int i = 0; i < 32; i += 8)
        tile[ty + i][tx] = w[(size_t)(by + ty + i) * DDIM + bx + tx];
    __syncthreads();
#pragma unroll
    for (int i = 0; i < 32; i += 8) {
        float v = tile[tx][ty + i];
        size_t o = (size_t)(bx + ty + i) * DDIM + by + tx;
        __nv_bfloat16 h = __float2bfloat16(v);
        hi[o] = h;
        lo[o] = __float2bfloat16(v - __bfloat162float(h));
    }
}

// ---------------------------------------------------------------------------
// Tensor-core GEMM via mma.sync (bf16 3-pass split, fp32 accum)
// ---------------------------------------------------------------------------
#define KP 40

__global__ void __launch_bounds__(256) mma_gemm(
    const __nv_bfloat16* __restrict__ Ah, const __nv_bfloat16* __restrict__ Al,
    const __nv_bfloat16* __restrict__ Bh, const __nv_bfloat16* __restrict__ Bl,
    const float* __restrict__ bias, float* __restrict__ C)
{
    __shared__ __nv_bfloat16 sAh[128][KP], sAl[128][KP];
    __shared__ __nv_bfloat16 sBh[128][KP], sBl[128][KP];

    const int tid = threadIdx.x;
    const int lane = tid & 31;
    const int wid = tid >> 5;
    const int wm = (wid & 1) * 64;
    const int wn = (wid >> 1) * 32;
    const int bn = blockIdx.x * 128;
    const int bm = blockIdx.y * 128;

    float acc[4][4][4];
#pragma unroll
    for (int i = 0; i < 4; i++)
#pragma unroll
        for (int j = 0; j < 4; j++)
#pragma unroll
            for (int r = 0; r < 4; r++) acc[i][j][r] = 0.f;

    const int a_row = lane & 15;
    const int a_kof = (lane >> 4) << 3;
    const int b_n   = (lane & 7) + ((lane >> 4) << 3);
    const int b_kof = ((lane >> 3) & 1) << 3;

    const int ld_row = tid >> 2;
    const int ld_cg  = (tid & 3) * 8;

    for (int kt = 0; kt < 32; kt++) {
        const int k0 = kt * 32;
#pragma unroll
        for (int half = 0; half < 2; half++) {
            int row = half * 64 + ld_row;
            size_t ga = (size_t)(bm + row) * DDIM + k0 + ld_cg;
            size_t gb = (size_t)(bn + row) * DDIM + k0 + ld_cg;
            *(uint4*)&sAh[row][ld_cg] = *(const uint4*)(Ah + ga);
            *(uint4*)&sAl[row][ld_cg] = *(const uint4*)(Al + ga);
            *(uint4*)&sBh[row][ld_cg] = *(const uint4*)(Bh + gb);
            *(uint4*)&sBl[row][ld_cg] = *(const uint4*)(Bl + gb);
        }
        __syncthreads();

#pragma unroll
        for (int ko = 0; ko < 32; ko += 16) {
            uint32_t bh[4][2], bl[4][2];
#pragma unroll
            for (int p = 0; p < 2; p++) {
                uint32_t t4[4];
                uint32_t addr = smem_u32(&sBh[wn + p * 16 + b_n][ko + b_kof]);
                ldm_x4(t4, addr);
                bh[p * 2][0] = t4[0]; bh[p * 2][1] = t4[1];
                bh[p * 2 + 1][0] = t4[2]; bh[p * 2 + 1][1] = t4[3];
                addr = smem_u32(&sBl[wn + p * 16 + b_n][ko + b_kof]);
                ldm_x4(t4, addr);
                bl[p * 2][0] = t4[0]; bl[p * 2][1] = t4[1];
                bl[p * 2 + 1][0] = t4[2]; bl[p * 2 + 1][1] = t4[3];
            }
#pragma unroll
            for (int mf = 0; mf < 4; mf++) {
                uint32_t ahr[4], alr[4];
                ldm_x4(ahr, smem_u32(&sAh[wm + mf * 16 + a_row][ko + a_kof]));
                ldm_x4(alr, smem_u32(&sAl[wm + mf * 16 + a_row][ko + a_kof]));
#pragma unroll
                for (int nf = 0; nf < 4; nf++) {
                    mma16816(acc[mf][nf], ahr, bh[nf]);
                    mma16816(acc[mf][nf], ahr, bl[nf]);
                    mma16816(acc[mf][nf], alr, bh[nf]);
                }
            }
        }
        __syncthreads();
    }

    const int qr = lane >> 2;
    const int qc = (lane & 3) * 2;
#pragma unroll
    for (int mf = 0; mf < 4; mf++) {
#pragma unroll
        for (int nf = 0; nf < 4; nf++) {
            int col = bn + wn + nf * 8 + qc;
            float b0 = bias[col], b1 = bias[col + 1];
            int r0 = bm + wm + mf * 16 + qr;
            float2 v0 = {acc[mf][nf][0] + b0, acc[mf][nf][1] + b1};
            float2 v1 = {acc[mf][nf][2] + b0, acc[mf][nf][3] + b1};
            *(float2*)&C[(size_t)r0 * DDIM + col] = v0;
            *(float2*)&C[(size_t)(r0 + 8) * DDIM + col] = v1;
        }
    }
}

// ---------------------------------------------------------------------------
// RoPE + bf16 hi/lo split for Q,K (fused)
// ---------------------------------------------------------------------------
__global__ void rope_split_kernel() {
    int idx = blockIdx.x * blockDim.x + threadIdx.x;
    const int total = BB * TT * HH * 32;
    if (idx >= total) return;
    int j = idx & 31;
    int h = (idx >> 5) & (HH - 1);
    int t = (idx >> 9) & (TT - 1);
    int b = idx >> 20;

    size_t off = ((size_t)(b * TT + t)) * DDIM + h * DHH;
    int ti = t * 32;
    float c1 = g_cos[ti + (j >> 1)];
    float s1 = g_sin[ti + (j >> 1)];
    float c2 = g_cos[ti + (j >> 1) + 16];
    float s2 = g_sin[ti + (j >> 1) + 16];

    float q1 = g_q[off + j], q2 = g_q[off + j + 32];
    float qa = q1 * c1 - q2 * s1;
    float qb = q2 * c2 + q1 * s2;
    __nv_bfloat16 hq1 = __float2bfloat16(qa);
    __nv_bfloat16 hq2 = __float2bfloat16(qb);
    g_qhi[off + j]      = hq1;
    g_qhi[off + j + 32] = hq2;
    g_qlo[off + j]      = __float2bfloat16(qa - __bfloat162float(hq1));
    g_qlo[off + j + 32] = __float2bfloat16(qb - __bfloat162float(hq2));

    float k1 = g_k[off + j], k2 = g_k[off + j + 32];
    float ka = k1 * c1 - k2 * s1;
    float kb = k2 * c2 + k1 * s2;
    __nv_bfloat16 hk1 = __float2bfloat16(ka);
    __nv_bfloat16 hk2 = __float2bfloat16(kb);
    g_khi[off + j]      = hk1;
    g_khi[off + j + 32] = hk2;
    g_klo[off + j]      = __float2bfloat16(ka - __bfloat162float(hk1));
    g_klo[off + j + 32] = __float2bfloat16(kb - __bfloat162float(hk2));
}

// ---------------------------------------------------------------------------
// V transpose + split: g_v[b,t,h,dh] -> g_vt{hi,lo}[b,h,dh,T]
// ---------------------------------------------------------------------------
__global__ void vsplitT_kernel() {
    __shared__ float tile[32][33];
    int t0 = blockIdx.x * 32;
    int d0 = blockIdx.y * 32;      // 0 or 32
    int bh = blockIdx.z;           // b*HH + h
    int b = bh / HH, h = bh % HH;
    int tx = threadIdx.x, ty = threadIdx.y;  // 32 x 8
#pragma unroll
    for (int i = 0; i < 32; i += 8)
        tile[ty + i][tx] = g_v[((size_t)b * TT + t0 + ty + i) * DDIM + h * DHH + d0 + tx];
    __syncthreads();
#pragma unroll
    for (int i = 0; i < 32; i += 8) {
        float v = tile[tx][ty + i];   // element (t = t0+tx, d = d0+ty+i)
        size_t o = ((size_t)bh * DHH + d0 + ty + i) * TT + t0 + tx;
        __nv_bfloat16 hv = __float2bfloat16(v);
        g_vthi[o] = hv;
        g_vtlo[o] = __float2bfloat16(v - __bfloat162float(hv));
    }
}

// ---------------------------------------------------------------------------
// Flash attention with mma.sync, 3-pass bf16 split for S and PV.
// Block: 128 q-rows x (b,h). 8 warps, each m16. k-tiles of 64.
// ---------------------------------------------------------------------------
#define AP 72  // smem row stride (bf16)

__global__ void __launch_bounds__(256) attn_mma_kernel() {
    __shared__ __nv_bfloat16 sm[18432];  // 36 KB; Q area reused for K/V
    __nv_bfloat16* sQh = sm;             // [128][72]
    __nv_bfloat16* sQl = sm + 9216;
    __nv_bfloat16* sKh = sm;             // [64][72] (after Q consumed)
    __nv_bfloat16* sKl = sm + 4608;
    __nv_bfloat16* sVh = sm + 9216;      // Vt [64(dh)][72]
    __nv_bfloat16* sVl = sm + 13824;

    const int q0 = blockIdx.x * 128;
    const int h  = blockIdx.y;
    const int b  = blockIdx.z;
    const int tid = threadIdx.x;
    const int lane = tid & 31;
    const int wid = tid >> 5;
    const int wm = wid * 16;

    const size_t base_qk = (size_t)b * TT * DDIM + (size_t)h * DHH;
    const size_t base_vt = ((size_t)(b * HH + h)) * DHH * TT;

    const int a_row = lane & 15;
    const int a_kof = (lane >> 4) << 3;
    const int b_n   = (lane & 7) + ((lane >> 4) << 3);
    const int b_kof = ((lane >> 3) & 1) << 3;

    // ---- stage Q tile, load Q fragments to registers ----
    {
        const int r = tid >> 1;               // 0..127
        const int c = (tid & 1) * 32;         // two uint4 groups... use loop
        (void)r; (void)c;
    }
    for (int i = tid; i < 128 * 8; i += 256) {
        int r = i >> 3, c = (i & 7) * 8;
        size_t g = base_qk + (size_t)(q0 + r) * DDIM + c;
        *(uint4*)&sQh[r * AP + c] = *(const uint4*)&g_qhi[g];
        *(uint4*)&sQl[r * AP + c] = *(const uint4*)&g_qlo[g];
    }
    __syncthreads();

    uint32_t qh[4][4], ql[4][4];
#pragma unroll
    for (int ko = 0; ko < 4; ko++) {
        ldm_x4(qh[ko], smem_u32(&sQh[(wm + a_row) * AP + ko * 16 + a_kof]));
        ldm_x4(ql[ko], smem_u32(&sQl[(wm + a_row) * AP + ko * 16 + a_kof]));
    }
    __syncthreads();  // Q smem free for K/V reuse

    float m0 = -CUDART_INF_F, m1 = -CUDART_INF_F;
    float l0 = 0.f, l1 = 0.f;
    float o[8][4];
#pragma unroll
    for (int nf = 0; nf < 8; nf++)
#pragma unroll
        for (int r = 0; r < 4; r++) o[nf][r] = 0.f;

    const int nkt = q0 / 64 + 2;
    const float scale = 0.125f;

    for (int kt = 0; kt < nkt; kt++) {
        const int k0 = kt * 64;
        // stage K and Vt tiles (hi/lo)
        for (int i = tid; i < 64 * 8; i += 256) {
            int r = i >> 3, c = (i & 7) * 8;
            size_t gk = base_qk + (size_t)(k0 + r) * DDIM + c;
            *(uint4*)&sKh[r * AP + c] = *(const uint4*)&g_khi[gk];
            *(uint4*)&sKl[r * AP + c] = *(const uint4*)&g_klo[gk];
            size_t gv = base_vt + (size_t)r * TT + k0 + c;
            *(uint4*)&sVh[r * AP + c] = *(const uint4*)&g_vthi[gv];
            *(uint4*)&sVl[r * AP + c] = *(const uint4*)&g_vtlo[gv];
        }
        __syncthreads();

        if (k0 <= q0 + wm + 15) {  // tile not fully masked for this warp
            // ---- S = Q K^T (3-pass) ----
            float s[8][4];
#pragma unroll
            for (int nf = 0; nf < 8; nf++)
#pragma unroll
                for (int r = 0; r < 4; r++) s[nf][r] = 0.f;

#pragma unroll
            for (int ko = 0; ko < 4; ko++) {
#pragma unroll
                for (int p = 0; p < 4; p++) {
                    uint32_t th[4], tl[4];
                    ldm_x4(th, smem_u32(&sKh[(p * 16 + b_n) * AP + ko * 16 + b_kof]));
                    ldm_x4(tl, smem_u32(&sKl[(p * 16 + b_n) * AP + ko * 16 + b_kof]));
                    mma16816(s[2 * p],     qh[ko], th);
                    mma16816(s[2 * p],     qh[ko], tl);
                    mma16816(s[2 * p],     ql[ko], th);
                    mma16816(s[2 * p + 1], qh[ko], th + 2);
                    mma16816(s[2 * p + 1], qh[ko], tl + 2);
                    mma16816(s[2 * p + 1], ql[ko], th + 2);
                }
            }

            // ---- scale + causal mask ----
            const int qa = q0 + wm + (lane >> 2);
            const int qb = qa + 8;
            const bool need_mask = (k0 + 63 > q0 + wm);
#pragma unroll
            for (int nf = 0; nf < 8; nf++) {
                int cg = k0 + nf * 8 + (lane & 3) * 2;
                s[nf][0] *= scale; s[nf][1] *= scale;
                s[nf][2] *= scale; s[nf][3] *= scale;
                if (need_mask) {
                    if (cg > qa)     s[nf][0] = -10000.f;
                    if (cg + 1 > qa) s[nf][1] = -10000.f;
                    if (cg > qb)     s[nf][2] = -10000.f;
                    if (cg + 1 > qb) s[nf][3] = -10000.f;
                }
            }

            // ---- online softmax ----
            float rma = -CUDART_INF_F, rmb = -CUDART_INF_F;
#pragma unroll
            for (int nf = 0; nf < 8; nf++) {
                rma = fmaxf(rma, fmaxf(s[nf][0], s[nf][1]));
                rmb = fmaxf(rmb, fmaxf(s[nf][2], s[nf][3]));
            }
            rma = fmaxf(rma, __shfl_xor_sync(0xffffffffu, rma, 1));
            rma = fmaxf(rma, __shfl_xor_sync(0xffffffffu, rma, 2));
            rmb = fmaxf(rmb, __shfl_xor_sync(0xffffffffu, rmb, 1));
            rmb = fmaxf(rmb, __shfl_xor_sync(0xffffffffu, rmb, 2));
            float nma = fmaxf(m0, rma), nmb = fmaxf(m1, rmb);
            float alpha_a = __expf(m0 - nma), alpha_b = __expf(m1 - nmb);
            m0 = nma; m1 = nmb;

            float rsa = 0.f, rsb = 0.f;
#pragma unroll
            for (int nf = 0; nf < 8; nf++) {
                s[nf][0] = __expf(s[nf][0] - nma);
                s[nf][1] = __expf(s[nf][1] - nma);
                s[nf][2] = __expf(s[nf][2] - nmb);
                s[nf][3] = __expf(s[nf][3] - nmb);
                rsa += s[nf][0] + s[nf][1];
                rsb += s[nf][2] + s[nf][3];
            }
            rsa += __shfl_xor_sync(0xffffffffu, rsa, 1);
            rsa += __shfl_xor_sync(0xffffffffu, rsa, 2);
            rsb += __shfl_xor_sync(0xffffffffu, rsb, 1);
            rsb += __shfl_xor_sync(0xffffffffu, rsb, 2);
            l0 = l0 * alpha_a + rsa;
            l1 = l1 * alpha_b + rsb;

#pragma unroll
            for (int nf = 0; nf < 8; nf++) {
                o[nf][0] *= alpha_a; o[nf][1] *= alpha_a;
                o[nf][2] *= alpha_b; o[nf][3] *= alpha_b;
            }

            // ---- P fragments (bf16 hi/lo) from S fragments ----
            uint32_t ph[4][4], pl[4][4];
#pragma unroll
            for (int kb = 0; kb < 4; kb++) {
                float* f0 = s[2 * kb];
                float* f1 = s[2 * kb + 1];
                ph[kb][0] = cvt_bf2(f0[0], f0[1]);
                ph[kb][1] = cvt_bf2(f0[2], f0[3]);
                ph[kb][2] = cvt_bf2(f1[0], f1[1]);
                ph[kb][3] = cvt_bf2(f1[2], f1[3]);
                float2 u;
                u = unpack_bf2(ph[kb][0]); pl[kb][0] = cvt_bf2(f0[0] - u.x, f0[1] - u.y);
                u = unpack_bf2(ph[kb][1]); pl[kb][1] = cvt_bf2(f0[2] - u.x, f0[3] - u.y);
                u = unpack_bf2(ph[kb][2]); pl[kb][2] = cvt_bf2(f1[0] - u.x, f1[1] - u.y);
                u = unpack_bf2(ph[kb][3]); pl[kb][3] = cvt_bf2(f1[2] - u.x, f1[3] - u.y);
            }

            // ---- O += P V (3-pass) ----
#pragma unroll
            for (int kb = 0; kb < 4; kb++) {
#pragma unroll
                for (int p = 0; p < 4; p++) {
                    uint32_t th[4], tl[4];
                    ldm_x4(th, smem_u32(&sVh[(p * 16 + b_n) * AP + kb * 16 + b_kof]));
                    ldm_x4(tl, smem_u32(&sVl[(p * 16 + b_n) * AP + kb * 16 + b_kof]));
                    mma16816(o[2 * p],     ph[kb], th);
                    mma16816(o[2 * p],     ph[kb], tl);
                    mma16816(o[2 * p],     pl[kb], th);
                    mma16816(o[2 * p + 1], ph[kb], th + 2);
                    mma16816(o[2 * p + 1], ph[kb], tl + 2);
                    mma16816(o[2 * p + 1], pl[kb], th + 2);
                }
            }
        }
        __syncthreads();
    }

    // ---- epilogue: normalize, write to g_att[b,t,h*64+d] ----
    float inv_a = 1.0f / l0, inv_b = 1.0f / l1;
    int ra = q0 + wm + (lane >> 2);
    int cq = (lane & 3) * 2;
#pragma unroll
    for (int nf = 0; nf < 8; nf++) {
        int col = h * DHH + nf * 8 + cq;
        float2 v0 = {o[nf][0] * inv_a, o[nf][1] * inv_a};
        float2 v1 = {o[nf][2] * inv_b, o[nf][3] * inv_b};
        *(float2*)&g_att[((size_t)b * TT + ra) * DDIM + col] = v0;
        *(float2*)&g_att[((size_t)b * TT + ra + 8) * DDIM + col] = v1;
    }
}

// ---------------------------------------------------------------------------
// Launch
// ---------------------------------------------------------------------------
extern "C" void kernel_launch(void* const* d_in, const int* in_sizes, int n_in,
                              void* d_out, int out_size)
{
    const float* x  = (const float*)d_in[0];
    const float* wq = (const float*)d_in[2];
    const float* bq = (const float*)d_in[3];
    const float* wk = (const float*)d_in[4];
    const float* bk = (const float*)d_in[5];
    const float* wv = (const float*)d_in[6];
    const float* bv = (const float*)d_in[7];
    const float* wo = (const float*)d_in[8];
    const float* bo = (const float*)d_in[9];
    float* out = (float*)d_out;

    float *qp, *kp, *vp, *ap;
    __nv_bfloat16 *ahi, *alo, *whi, *wlo;
    cudaGetSymbolAddress((void**)&qp, g_q);
    cudaGetSymbolAddress((void**)&kp, g_k);
    cudaGetSymbolAddress((void**)&vp, g_v);
    cudaGetSymbolAddress((void**)&ap, g_att);
    cudaGetSymbolAddress((void**)&ahi, g_ahi);
    cudaGetSymbolAddress((void**)&alo, g_alo);
    cudaGetSymbolAddress((void**)&whi, g_whi);
    cudaGetSymbolAddress((void**)&wlo, g_wlo);

    const size_t WSZ = (size_t)DDIM * DDIM;

    sincos_kernel<<<(TT * 32 + 255) / 256, 256>>>();

    const int n_act = MM * DDIM;
    split_kernel<<<(n_act + 255) / 256, 256>>>(x, ahi, alo, n_act);
    dim3 tgrid(32, 32), tblk(32, 8);
    splitT_kernel<<<tgrid, tblk>>>(wq, whi + 0 * WSZ, wlo + 0 * WSZ);
    splitT_kernel<<<tgrid, tblk>>>(wk, whi + 1 * WSZ, wlo + 1 * WSZ);
    splitT_kernel<<<tgrid, tblk>>>(wv, whi + 2 * WSZ, wlo + 2 * WSZ);
    splitT_kernel<<<tgrid, tblk>>>(wo, whi + 3 * WSZ, wlo + 3 * WSZ);

    dim3 ggrid(DDIM / 128, MM / 128);
    mma_gemm<<<ggrid, 256>>>(ahi, alo, whi + 0 * WSZ, wlo + 0 * WSZ, bq, qp);
    mma_gemm<<<ggrid, 256>>>(ahi, alo, whi + 1 * WSZ, wlo + 1 * WSZ, bk, kp);
    mma_gemm<<<ggrid, 256>>>(ahi, alo, whi + 2 * WSZ, wlo + 2 * WSZ, bv, vp);

    // RoPE + split q,k ; transpose + split v
    const int rope_n = BB * TT * HH * 32;
    rope_split_kernel<<<(rope_n + 255) / 256, 256>>>();
    vsplitT_kernel<<<dim3(TT / 32, DHH / 32, BB * HH), dim3(32, 8)>>>();

    // tensor-core flash attention
    attn_mma_kernel<<<dim3(TT / 128, HH, BB), 256>>>();

    // out-projection
    split_kernel<<<(n_act + 255) / 256, 256>>>(ap, ahi, alo, n_act);
    mma_gemm<<<ggrid, 256>>>(ahi, alo, whi + 3 * WSZ, wlo + 3 * WSZ, bo, out);
}

// round 7
// speedup vs baseline: 3.0688x; 1.3940x over previous
#include <cuda_runtime.h>
#include <cuda_bf16.h>
#include <math.h>
#include <math_constants.h>
#include <cstdint>

// Problem constants
#define BB  2
#define TT  2048
#define DDIM 1024
#define HH  16
#define DHH 64
#define MM  (BB*TT)

// ---------------------------------------------------------------------------
// Scratch (device globals)
// ---------------------------------------------------------------------------
__device__ float g_q[(size_t)MM * DDIM];
__device__ float g_k[(size_t)MM * DDIM];
__device__ float g_v[(size_t)MM * DDIM];
__device__ float g_sin[TT * 32];
__device__ float g_cos[TT * 32];

__device__ __nv_bfloat16 g_ahi[(size_t)MM * DDIM];
__device__ __nv_bfloat16 g_alo[(size_t)MM * DDIM];
__device__ __nv_bfloat16 g_whi[(size_t)4 * DDIM * DDIM];
__device__ __nv_bfloat16 g_wlo[(size_t)4 * DDIM * DDIM];

// attention bf16 operands
__device__ __nv_bfloat16 g_qhi[(size_t)MM * DDIM];
__device__ __nv_bfloat16 g_qlo[(size_t)MM * DDIM];
__device__ __nv_bfloat16 g_khi[(size_t)MM * DDIM];
__device__ __nv_bfloat16 g_klo[(size_t)MM * DDIM];
__device__ __nv_bfloat16 g_vthi[(size_t)MM * DDIM];  // [b,h,dh,T]
__device__ __nv_bfloat16 g_vtlo[(size_t)MM * DDIM];

// ---------------------------------------------------------------------------
// Warp tensor helpers (baseline PTX: ldmatrix + mma.sync + cp.async)
// ---------------------------------------------------------------------------
__device__ __forceinline__ uint32_t smem_u32(const void* p) {
    uint32_t a;
    asm("{ .reg .u64 t; cvta.to.shared.u64 t, %1; cvt.u32.u64 %0, t; }"
        : "=r"(a) : "l"(p));
    return a;
}

__device__ __forceinline__ void ldm_x4(uint32_t* r, uint32_t addr) {
    asm volatile("ldmatrix.sync.aligned.m8n8.x4.shared.b16 {%0,%1,%2,%3}, [%4];"
                 : "=r"(r[0]), "=r"(r[1]), "=r"(r[2]), "=r"(r[3]) : "r"(addr));
}

__device__ __forceinline__ void mma16816(float* c, const uint32_t* a,
                                         const uint32_t* b) {
    asm volatile(
        "mma.sync.aligned.m16n8k16.row.col.f32.bf16.bf16.f32 "
        "{%0,%1,%2,%3}, {%4,%5,%6,%7}, {%8,%9}, {%0,%1,%2,%3};"
        : "+f"(c[0]), "+f"(c[1]), "+f"(c[2]), "+f"(c[3])
        : "r"(a[0]), "r"(a[1]), "r"(a[2]), "r"(a[3]), "r"(b[0]), "r"(b[1]));
}

__device__ __forceinline__ void cp16(uint32_t dst, const void* src) {
    asm volatile("cp.async.cg.shared.global [%0], [%1], 16;"
                 :: "r"(dst), "l"(src));
}
#define CP_COMMIT() asm volatile("cp.async.commit_group;" ::: "memory")
#define CP_WAIT0()  asm volatile("cp.async.wait_group 0;" ::: "memory")

__device__ __forceinline__ uint32_t cvt_bf2(float lo, float hi) {
    uint32_t r;
    asm("cvt.rn.bf16x2.f32 %0, %1, %2;" : "=r"(r) : "f"(hi), "f"(lo));
    return r;
}
__device__ __forceinline__ float2 unpack_bf2(uint32_t v) {
    __nv_bfloat162 b = *reinterpret_cast<__nv_bfloat162*>(&v);
    return __bfloat1622float2(b);
}

// ---------------------------------------------------------------------------
// RoPE sin/cos table
// ---------------------------------------------------------------------------
__global__ void sincos_kernel() {
    int idx = blockIdx.x * blockDim.x + threadIdx.x;
    if (idx >= TT * 32) return;
    int t  = idx >> 5;
    int jj = idx & 31;
    double ang = (double)t * pow(10000.0, -2.0 * (double)jj / 64.0);
    g_sin[idx] = (float)sin(ang);
    g_cos[idx] = (float)cos(ang);
}

// ---------------------------------------------------------------------------
// fp32 -> bf16 hi/lo split (vectorized)
// ---------------------------------------------------------------------------
__global__ void split_kernel(const float* __restrict__ src,
                             __nv_bfloat16* __restrict__ hi,
                             __nv_bfloat16* __restrict__ lo, int n4) {
    int i = blockIdx.x * blockDim.x + threadIdx.x;
    if (i >= n4) return;
    float4 v = ((const float4*)src)[i];
    __nv_bfloat16 h0 = __float2bfloat16(v.x), h1 = __float2bfloat16(v.y);
    __nv_bfloat16 h2 = __float2bfloat16(v.z), h3 = __float2bfloat16(v.w);
    uint2 hh, ll;
    hh.x = cvt_bf2(v.x, v.y); hh.y = cvt_bf2(v.z, v.w);
    ll.x = cvt_bf2(v.x - __bfloat162float(h0), v.y - __bfloat162float(h1));
    ll.y = cvt_bf2(v.z - __bfloat162float(h2), v.w - __bfloat162float(h3));
    ((uint2*)hi)[i] = hh;
    ((uint2*)lo)[i] = ll;
}

// fp32 W[K,N] -> bf16 hi/lo transposed [N,K]
__global__ void splitT_kernel(const float* __restrict__ w,
                              __nv_bfloat16* __restrict__ hi,
                              __nv_bfloat16* __restrict__ lo) {
    __shared__ float tile[32][33];
    int bx = blockIdx.x * 32;
    int by = blockIdx.y * 32;
    int tx = threadIdx.x, ty = threadIdx.y;
#pragma unroll
    for (int i = 0; i < 32; i += 8)
        tile[ty + i][tx] = w[(size_t)(by + ty + i) * DDIM + bx + tx];
    __syncthreads();
#pragma unroll
    for (int i = 0; i < 32; i += 8) {
        float v = tile[tx][ty + i];
        size_t o = (size_t)(bx + ty + i) * DDIM + by + tx;
        __nv_bfloat16 h = __float2bfloat16(v);
        hi[o] = h;
        lo[o] = __float2bfloat16(v - __bfloat162float(h));
    }
}

// ---------------------------------------------------------------------------
// Tensor-core GEMM, cp.async double-buffered (bf16 3-pass split, fp32 accum)
// Block 128x128, 8 warps (warp tile 64x32), kTile=32.
// ---------------------------------------------------------------------------
#define GT_ROW 80        // bytes per smem row (40 bf16)
#define GT_ARR 10240     // bytes per tile array (128*80)
#define GT_BUF 40960     // bytes per stage (4 arrays)
#define GEMM_SMEM (2 * GT_BUF)

__global__ void __launch_bounds__(256) mma_gemm(
    const __nv_bfloat16* __restrict__ Ah, const __nv_bfloat16* __restrict__ Al,
    const __nv_bfloat16* __restrict__ Bh, const __nv_bfloat16* __restrict__ Bl,
    const float* __restrict__ bias, float* __restrict__ C)
{
    extern __shared__ char gsm[];
    const uint32_t sb = smem_u32(gsm);

    const int tid = threadIdx.x;
    const int lane = tid & 31;
    const int wid = tid >> 5;
    const int wm = (wid & 1) * 64;
    const int wn = (wid >> 1) * 32;
    const int bn = blockIdx.x * 128;
    const int bm = blockIdx.y * 128;

    float acc[4][4][4];
#pragma unroll
    for (int i = 0; i < 4; i++)
#pragma unroll
        for (int j = 0; j < 4; j++)
#pragma unroll
            for (int r = 0; r < 4; r++) acc[i][j][r] = 0.f;

    const int a_row = lane & 15;
    const int a_kof = (lane >> 4) << 3;
    const int b_n   = (lane & 7) + ((lane >> 4) << 3);
    const int b_kof = ((lane >> 3) & 1) << 3;

    const int ld_row = tid >> 2;       // 0..63
    const int ld_cg  = (tid & 3) * 8;  // bf16 col: 0,8,16,24

#define G_LOAD(kt, buf) do {                                                  \
        int k0_ = (kt) * 32;                                                  \
        _Pragma("unroll")                                                     \
        for (int half = 0; half < 2; half++) {                                \
            int row_ = half * 64 + ld_row;                                    \
            size_t ga_ = (size_t)(bm + row_) * DDIM + k0_ + ld_cg;            \
            size_t gb_ = (size_t)(bn + row_) * DDIM + k0_ + ld_cg;            \
            uint32_t so_ = sb + (buf) * GT_BUF + row_ * GT_ROW + ld_cg * 2;   \
            cp16(so_ + 0 * GT_ARR, Ah + ga_);                                 \
            cp16(so_ + 1 * GT_ARR, Al + ga_);                                 \
            cp16(so_ + 2 * GT_ARR, Bh + gb_);                                 \
            cp16(so_ + 3 * GT_ARR, Bl + gb_);                                 \
        } } while (0)

    G_LOAD(0, 0);
    CP_COMMIT();

    for (int kt = 0; kt < 32; kt++) {
        CP_WAIT0();
        __syncthreads();
        if (kt + 1 < 32) { G_LOAD(kt + 1, (kt + 1) & 1); CP_COMMIT(); }

        const uint32_t bufb = sb + (kt & 1) * GT_BUF;
#pragma unroll
        for (int ko = 0; ko < 32; ko += 16) {
            uint32_t bh[4][2], bl[4][2];
#pragma unroll
            for (int p = 0; p < 2; p++) {
                uint32_t t4[4];
                uint32_t boff = (wn + p * 16 + b_n) * GT_ROW + (ko + b_kof) * 2;
                ldm_x4(t4, bufb + 2 * GT_ARR + boff);
                bh[p * 2][0] = t4[0]; bh[p * 2][1] = t4[1];
                bh[p * 2 + 1][0] = t4[2]; bh[p * 2 + 1][1] = t4[3];
                ldm_x4(t4, bufb + 3 * GT_ARR + boff);
                bl[p * 2][0] = t4[0]; bl[p * 2][1] = t4[1];
                bl[p * 2 + 1][0] = t4[2]; bl[p * 2 + 1][1] = t4[3];
            }
#pragma unroll
            for (int mf = 0; mf < 4; mf++) {
                uint32_t ahr[4], alr[4];
                uint32_t aoff = (wm + mf * 16 + a_row) * GT_ROW + (ko + a_kof) * 2;
                ldm_x4(ahr, bufb + 0 * GT_ARR + aoff);
                ldm_x4(alr, bufb + 1 * GT_ARR + aoff);
#pragma unroll
                for (int nf = 0; nf < 4; nf++) {
                    mma16816(acc[mf][nf], ahr, bh[nf]);
                    mma16816(acc[mf][nf], ahr, bl[nf]);
                    mma16816(acc[mf][nf], alr, bh[nf]);
                }
            }
        }
        __syncthreads();
    }
#undef G_LOAD

    const int qr = lane >> 2;
    const int qc = (lane & 3) * 2;
#pragma unroll
    for (int mf = 0; mf < 4; mf++) {
#pragma unroll
        for (int nf = 0; nf < 4; nf++) {
            int col = bn + wn + nf * 8 + qc;
            float b0 = bias[col], b1 = bias[col + 1];
            int r0 = bm + wm + mf * 16 + qr;
            float2 v0 = {acc[mf][nf][0] + b0, acc[mf][nf][1] + b1};
            float2 v1 = {acc[mf][nf][2] + b0, acc[mf][nf][3] + b1};
            *(float2*)&C[(size_t)r0 * DDIM + col] = v0;
            *(float2*)&C[(size_t)(r0 + 8) * DDIM + col] = v1;
        }
    }
}

// ---------------------------------------------------------------------------
// RoPE + bf16 hi/lo split for Q,K (fused)
// ---------------------------------------------------------------------------
__global__ void rope_split_kernel() {
    int idx = blockIdx.x * blockDim.x + threadIdx.x;
    const int total = BB * TT * HH * 32;
    if (idx >= total) return;
    int j = idx & 31;
    int h = (idx >> 5) & (HH - 1);
    int t = (idx >> 9) & (TT - 1);
    int b = idx >> 20;

    size_t off = ((size_t)(b * TT + t)) * DDIM + h * DHH;
    int ti = t * 32;
    float c1 = g_cos[ti + (j >> 1)];
    float s1 = g_sin[ti + (j >> 1)];
    float c2 = g_cos[ti + (j >> 1) + 16];
    float s2 = g_sin[ti + (j >> 1) + 16];

    float q1 = g_q[off + j], q2 = g_q[off + j + 32];
    float qa = q1 * c1 - q2 * s1;
    float qb = q2 * c2 + q1 * s2;
    __nv_bfloat16 hq1 = __float2bfloat16(qa);
    __nv_bfloat16 hq2 = __float2bfloat16(qb);
    g_qhi[off + j]      = hq1;
    g_qhi[off + j + 32] = hq2;
    g_qlo[off + j]      = __float2bfloat16(qa - __bfloat162float(hq1));
    g_qlo[off + j + 32] = __float2bfloat16(qb - __bfloat162float(hq2));

    float k1 = g_k[off + j], k2 = g_k[off + j + 32];
    float ka = k1 * c1 - k2 * s1;
    float kb = k2 * c2 + k1 * s2;
    __nv_bfloat16 hk1 = __float2bfloat16(ka);
    __nv_bfloat16 hk2 = __float2bfloat16(kb);
    g_khi[off + j]      = hk1;
    g_khi[off + j + 32] = hk2;
    g_klo[off + j]      = __float2bfloat16(ka - __bfloat162float(hk1));
    g_klo[off + j + 32] = __float2bfloat16(kb - __bfloat162float(hk2));
}

// ---------------------------------------------------------------------------
// V transpose + split: g_v[b,t,h,dh] -> g_vt{hi,lo}[b,h,dh,T]
// ---------------------------------------------------------------------------
__global__ void vsplitT_kernel() {
    __shared__ float tile[32][33];
    int t0 = blockIdx.x * 32;
    int d0 = blockIdx.y * 32;
    int bh = blockIdx.z;
    int b = bh / HH, h = bh % HH;
    int tx = threadIdx.x, ty = threadIdx.y;
#pragma unroll
    for (int i = 0; i < 32; i += 8)
        tile[ty + i][tx] = g_v[((size_t)b * TT + t0 + ty + i) * DDIM + h * DHH + d0 + tx];
    __syncthreads();
#pragma unroll
    for (int i = 0; i < 32; i += 8) {
        float v = tile[tx][ty + i];
        size_t o = ((size_t)bh * DHH + d0 + ty + i) * TT + t0 + tx;
        __nv_bfloat16 hv = __float2bfloat16(v);
        g_vthi[o] = hv;
        g_vtlo[o] = __float2bfloat16(v - __bfloat162float(hv));
    }
}

// ---------------------------------------------------------------------------
// Flash attention with mma.sync, cp.async double-buffered K/V staging.
// Block: 128 q-rows x (b,h). 8 warps, each m16. k-tiles of 64.
// Epilogue writes bf16 hi/lo directly (feeds out-proj GEMM).
// ---------------------------------------------------------------------------
#define AT_ROW 144       // bytes per smem row (72 bf16)
#define AT_ARR 9216      // bytes per K/V array (64*144)
#define AT_BUF 36864     // 4 arrays per stage
#define ATTN_SMEM (2 * AT_BUF)

__global__ void __launch_bounds__(256) attn_mma_kernel() {
    extern __shared__ char gsm[];
    const uint32_t sb = smem_u32(gsm);

    const int q0 = blockIdx.x * 128;
    const int h  = blockIdx.y;
    const int b  = blockIdx.z;
    const int tid = threadIdx.x;
    const int lane = tid & 31;
    const int wid = tid >> 5;
    const int wm = wid * 16;

    const size_t base_qk = (size_t)b * TT * DDIM + (size_t)h * DHH;
    const size_t base_vt = ((size_t)(b * HH + h)) * DHH * TT;

    const int a_row = lane & 15;
    const int a_kof = (lane >> 4) << 3;
    const int b_n   = (lane & 7) + ((lane >> 4) << 3);
    const int b_kof = ((lane >> 3) & 1) << 3;

    // ---- stage Q tile (uses stage-0 region), load Q frags to registers ----
    for (int i = tid; i < 128 * 8; i += 256) {
        int r = i >> 3, c = (i & 7) * 8;
        size_t g = base_qk + (size_t)(q0 + r) * DDIM + c;
        *(uint4*)(gsm + r * AT_ROW + c * 2) = *(const uint4*)&g_qhi[g];
        *(uint4*)(gsm + 18432 + r * AT_ROW + c * 2) = *(const uint4*)&g_qlo[g];
    }
    __syncthreads();

    uint32_t qh[4][4], ql[4][4];
#pragma unroll
    for (int ko = 0; ko < 4; ko++) {
        uint32_t aoff = (wm + a_row) * AT_ROW + (ko * 16 + a_kof) * 2;
        ldm_x4(qh[ko], sb + aoff);
        ldm_x4(ql[ko], sb + 18432 + aoff);
    }
    __syncthreads();  // Q smem consumed; region reused by K/V stages

    float m0 = -CUDART_INF_F, m1 = -CUDART_INF_F;
    float l0 = 0.f, l1 = 0.f;
    float o[8][4];
#pragma unroll
    for (int nf = 0; nf < 8; nf++)
#pragma unroll
        for (int r = 0; r < 4; r++) o[nf][r] = 0.f;

    const int nkt = q0 / 64 + 2;
    const float scale = 0.125f;

#define A_LOAD(kt, buf) do {                                                  \
        int k0_ = (kt) * 64;                                                  \
        _Pragma("unroll")                                                     \
        for (int i = tid; i < 512; i += 256) {                                \
            int r_ = i >> 3, c_ = (i & 7) * 8;                                \
            uint32_t so_ = sb + (buf) * AT_BUF + r_ * AT_ROW + c_ * 2;        \
            size_t gk_ = base_qk + (size_t)(k0_ + r_) * DDIM + c_;            \
            size_t gv_ = base_vt + (size_t)r_ * TT + k0_ + c_;                \
            cp16(so_ + 0 * AT_ARR, g_khi + gk_);                              \
            cp16(so_ + 1 * AT_ARR, g_klo + gk_);                              \
            cp16(so_ + 2 * AT_ARR, g_vthi + gv_);                             \
            cp16(so_ + 3 * AT_ARR, g_vtlo + gv_);                             \
        } } while (0)

    A_LOAD(0, 0);
    CP_COMMIT();

    for (int kt = 0; kt < nkt; kt++) {
        const int k0 = kt * 64;
        CP_WAIT0();
        __syncthreads();
        if (kt + 1 < nkt) { A_LOAD(kt + 1, (kt + 1) & 1); CP_COMMIT(); }

        const uint32_t bufb = sb + (kt & 1) * AT_BUF;

        if (k0 <= q0 + wm + 15) {
            // ---- S = Q K^T (3-pass) ----
            float s[8][4];
#pragma unroll
            for (int nf = 0; nf < 8; nf++)
#pragma unroll
                for (int r = 0; r < 4; r++) s[nf][r] = 0.f;

#pragma unroll
            for (int ko = 0; ko < 4; ko++) {
#pragma unroll
                for (int p = 0; p < 4; p++) {
                    uint32_t th[4], tl[4];
                    uint32_t boff = (p * 16 + b_n) * AT_ROW + (ko * 16 + b_kof) * 2;
                    ldm_x4(th, bufb + 0 * AT_ARR + boff);
                    ldm_x4(tl, bufb + 1 * AT_ARR + boff);
                    mma16816(s[2 * p],     qh[ko], th);
                    mma16816(s[2 * p],     qh[ko], tl);
                    mma16816(s[2 * p],     ql[ko], th);
                    mma16816(s[2 * p + 1], qh[ko], th + 2);
                    mma16816(s[2 * p + 1], qh[ko], tl + 2);
                    mma16816(s[2 * p + 1], ql[ko], th + 2);
                }
            }

            // ---- scale + causal mask ----
            const int qa = q0 + wm + (lane >> 2);
            const int qb = qa + 8;
            const bool need_mask = (k0 + 63 > q0 + wm);
#pragma unroll
            for (int nf = 0; nf < 8; nf++) {
                int cg = k0 + nf * 8 + (lane & 3) * 2;
                s[nf][0] *= scale; s[nf][1] *= scale;
                s[nf][2] *= scale; s[nf][3] *= scale;
                if (need_mask) {
                    if (cg > qa)     s[nf][0] = -10000.f;
                    if (cg + 1 > qa) s[nf][1] = -10000.f;
                    if (cg > qb)     s[nf][2] = -10000.f;
                    if (cg + 1 > qb) s[nf][3] = -10000.f;
                }
            }

            // ---- online softmax ----
            float rma = -CUDART_INF_F, rmb = -CUDART_INF_F;
#pragma unroll
            for (int nf = 0; nf < 8; nf++) {
                rma = fmaxf(rma, fmaxf(s[nf][0], s[nf][1]));
                rmb = fmaxf(rmb, fmaxf(s[nf][2], s[nf][3]));
            }
            rma = fmaxf(rma, __shfl_xor_sync(0xffffffffu, rma, 1));
            rma = fmaxf(rma, __shfl_xor_sync(0xffffffffu, rma, 2));
            rmb = fmaxf(rmb, __shfl_xor_sync(0xffffffffu, rmb, 1));
            rmb = fmaxf(rmb, __shfl_xor_sync(0xffffffffu, rmb, 2));
            float nma = fmaxf(m0, rma), nmb = fmaxf(m1, rmb);
            float alpha_a = __expf(m0 - nma), alpha_b = __expf(m1 - nmb);
            m0 = nma; m1 = nmb;

            float rsa = 0.f, rsb = 0.f;
#pragma unroll
            for (int nf = 0; nf < 8; nf++) {
                s[nf][0] = __expf(s[nf][0] - nma);
                s[nf][1] = __expf(s[nf][1] - nma);
                s[nf][2] = __expf(s[nf][2] - nmb);
                s[nf][3] = __expf(s[nf][3] - nmb);
                rsa += s[nf][0] + s[nf][1];
                rsb += s[nf][2] + s[nf][3];
            }
            rsa += __shfl_xor_sync(0xffffffffu, rsa, 1);
            rsa += __shfl_xor_sync(0xffffffffu, rsa, 2);
            rsb += __shfl_xor_sync(0xffffffffu, rsb, 1);
            rsb += __shfl_xor_sync(0xffffffffu, rsb, 2);
            l0 = l0 * alpha_a + rsa;
            l1 = l1 * alpha_b + rsb;

#pragma unroll
            for (int nf = 0; nf < 8; nf++) {
                o[nf][0] *= alpha_a; o[nf][1] *= alpha_a;
                o[nf][2] *= alpha_b; o[nf][3] *= alpha_b;
            }

            // ---- P fragments (bf16 hi/lo) from S fragments ----
            uint32_t ph[4][4], pl[4][4];
#pragma unroll
            for (int kb = 0; kb < 4; kb++) {
                float* f0 = s[2 * kb];
                float* f1 = s[2 * kb + 1];
                ph[kb][0] = cvt_bf2(f0[0], f0[1]);
                ph[kb][1] = cvt_bf2(f0[2], f0[3]);
                ph[kb][2] = cvt_bf2(f1[0], f1[1]);
                ph[kb][3] = cvt_bf2(f1[2], f1[3]);
                float2 u;
                u = unpack_bf2(ph[kb][0]); pl[kb][0] = cvt_bf2(f0[0] - u.x, f0[1] - u.y);
                u = unpack_bf2(ph[kb][1]); pl[kb][1] = cvt_bf2(f0[2] - u.x, f0[3] - u.y);
                u = unpack_bf2(ph[kb][2]); pl[kb][2] = cvt_bf2(f1[0] - u.x, f1[1] - u.y);
                u = unpack_bf2(ph[kb][3]); pl[kb][3] = cvt_bf2(f1[2] - u.x, f1[3] - u.y);
            }

            // ---- O += P V (3-pass) ----
#pragma unroll
            for (int kb = 0; kb < 4; kb++) {
#pragma unroll
                for (int p = 0; p < 4; p++) {
                    uint32_t th[4], tl[4];
                    uint32_t boff = (p * 16 + b_n) * AT_ROW + (kb * 16 + b_kof) * 2;
                    ldm_x4(th, bufb + 2 * AT_ARR + boff);
                    ldm_x4(tl, bufb + 3 * AT_ARR + boff);
                    mma16816(o[2 * p],     ph[kb], th);
                    mma16816(o[2 * p],     ph[kb], tl);
                    mma16816(o[2 * p],     pl[kb], th);
                    mma16816(o[2 * p + 1], ph[kb], th + 2);
                    mma16816(o[2 * p + 1], ph[kb], tl + 2);
                    mma16816(o[2 * p + 1], pl[kb], th + 2);
                }
            }
        }
        __syncthreads();
    }
#undef A_LOAD

    // ---- epilogue: normalize + write bf16 hi/lo directly (fused split) ----
    float inv_a = 1.0f / l0, inv_b = 1.0f / l1;
    int ra = q0 + wm + (lane >> 2);
    int cq = (lane & 3) * 2;
#pragma unroll
    for (int nf = 0; nf < 8; nf++) {
        int col = h * DHH + nf * 8 + cq;
        float v0 = o[nf][0] * inv_a, v1 = o[nf][1] * inv_a;
        float v2 = o[nf][2] * inv_b, v3 = o[nf][3] * inv_b;
        size_t o0 = ((size_t)b * TT + ra) * DDIM + col;
        size_t o1 = ((size_t)b * TT + ra + 8) * DDIM + col;
        uint32_t h0 = cvt_bf2(v0, v1), h1 = cvt_bf2(v2, v3);
        float2 u0 = unpack_bf2(h0), u1 = unpack_bf2(h1);
        uint32_t l0w = cvt_bf2(v0 - u0.x, v1 - u0.y);
        uint32_t l1w = cvt_bf2(v2 - u1.x, v3 - u1.y);
        *(uint32_t*)&g_ahi[o0] = h0;
        *(uint32_t*)&g_alo[o0] = l0w;
        *(uint32_t*)&g_ahi[o1] = h1;
        *(uint32_t*)&g_alo[o1] = l1w;
    }
}

// ---------------------------------------------------------------------------
// Launch
// ---------------------------------------------------------------------------
extern "C" void kernel_launch(void* const* d_in, const int* in_sizes, int n_in,
                              void* d_out, int out_size)
{
    const float* x  = (const float*)d_in[0];
    const float* wq = (const float*)d_in[2];
    const float* bq = (const float*)d_in[3];
    const float* wk = (const float*)d_in[4];
    const float* bk = (const float*)d_in[5];
    const float* wv = (const float*)d_in[6];
    const float* bv = (const float*)d_in[7];
    const float* wo = (const float*)d_in[8];
    const float* bo = (const float*)d_in[9];
    float* out = (float*)d_out;

    float *qp, *kp, *vp;
    __nv_bfloat16 *ahi, *alo, *whi, *wlo;
    cudaGetSymbolAddress((void**)&qp, g_q);
    cudaGetSymbolAddress((void**)&kp, g_k);
    cudaGetSymbolAddress((void**)&vp, g_v);
    cudaGetSymbolAddress((void**)&ahi, g_ahi);
    cudaGetSymbolAddress((void**)&alo, g_alo);
    cudaGetSymbolAddress((void**)&whi, g_whi);
    cudaGetSymbolAddress((void**)&wlo, g_wlo);

    const size_t WSZ = (size_t)DDIM * DDIM;

    sincos_kernel<<<(TT * 32 + 255) / 256, 256>>>();

    const int n4 = MM * DDIM / 4;
    split_kernel<<<(n4 + 255) / 256, 256>>>(x, ahi, alo, n4);
    dim3 tgrid(32, 32), tblk(32, 8);
    splitT_kernel<<<tgrid, tblk>>>(wq, whi + 0 * WSZ, wlo + 0 * WSZ);
    splitT_kernel<<<tgrid, tblk>>>(wk, whi + 1 * WSZ, wlo + 1 * WSZ);
    splitT_kernel<<<tgrid, tblk>>>(wv, whi + 2 * WSZ, wlo + 2 * WSZ);
    splitT_kernel<<<tgrid, tblk>>>(wo, whi + 3 * WSZ, wlo + 3 * WSZ);

    cudaFuncSetAttribute(mma_gemm, cudaFuncAttributeMaxDynamicSharedMemorySize,
                         GEMM_SMEM);
    dim3 ggrid(DDIM / 128, MM / 128);
    mma_gemm<<<ggrid, 256, GEMM_SMEM>>>(ahi, alo, whi + 0 * WSZ, wlo + 0 * WSZ, bq, qp);
    mma_gemm<<<ggrid, 256, GEMM_SMEM>>>(ahi, alo, whi + 1 * WSZ, wlo + 1 * WSZ, bk, kp);
    mma_gemm<<<ggrid, 256, GEMM_SMEM>>>(ahi, alo, whi + 2 * WSZ, wlo + 2 * WSZ, bv, vp);

    // RoPE + split q,k ; transpose + split v
    const int rope_n = BB * TT * HH * 32;
    rope_split_kernel<<<(rope_n + 255) / 256, 256>>>();
    vsplitT_kernel<<<dim3(TT / 32, DHH / 32, BB * HH), dim3(32, 8)>>>();

    // tensor-core flash attention (writes ahi/alo directly)
    cudaFuncSetAttribute(attn_mma_kernel,
                         cudaFuncAttributeMaxDynamicSharedMemorySize, ATTN_SMEM);
    attn_mma_kernel<<<dim3(TT / 128, HH, BB), 256, ATTN_SMEM>>>();

    // out-projection
    mma_gemm<<<ggrid, 256, GEMM_SMEM>>>(ahi, alo, whi + 3 * WSZ, wlo + 3 * WSZ, bo, out);
}